// round 14
// baseline (speedup 1.0000x reference)
#include <cuda_runtime.h>
#include <cuda_bf16.h>
#include <cstdint>
#include <math.h>

#define BATCH   32
#define NPTS    8192
#define NGROUPS 512
#define GSIZE   32
#define HDIM    128
#define EDIM    384

#define TOK_ELEMS (BATCH*NGROUPS*EDIM)   // 6291456
#define CEN_ELEMS (BATCH*NGROUPS*3)      // 49152
#define GID_ELEMS (BATCH*NGROUPS*GSIZE)  // 524288

// scratch (allocation-free rule: __device__ globals)
__device__ float g_centers[CEN_ELEMS];
__device__ int   g_gidx[GID_ELEMS];
// W2 k-pair-packed bf16x2 images: hi at [0, 24576), lo at [24576, 49152)
__device__ uint32_t g_w2p[49152];

// ---------------------------------------------------------------------------
// packed f32x2 helpers (FPS only)
// ---------------------------------------------------------------------------
__device__ __forceinline__ unsigned long long pack2(float a, float b) {
    unsigned long long r;
    asm("mov.b64 %0, {%1, %2};" : "=l"(r) : "f"(a), "f"(b));
    return r;
}
__device__ __forceinline__ void unpack2(unsigned long long v, float& a, float& b) {
    asm("mov.b64 {%0, %1}, %2;" : "=f"(a), "=f"(b) : "l"(v));
}
__device__ __forceinline__ unsigned long long add2(unsigned long long a, unsigned long long b) {
    unsigned long long r;
    asm("add.rn.f32x2 %0, %1, %2;" : "=l"(r) : "l"(a), "l"(b));
    return r;
}
__device__ __forceinline__ unsigned long long mul2(unsigned long long a, unsigned long long b) {
    unsigned long long r;
    asm("mul.rn.f32x2 %0, %1, %2;" : "=l"(r) : "l"(a), "l"(b));
    return r;
}
__device__ __forceinline__ unsigned long long fma2(unsigned long long a, unsigned long long b,
                                                   unsigned long long c) {
    unsigned long long r;
    asm("fma.rn.f32x2 %0, %1, %2, %3;" : "=l"(r) : "l"(a), "l"(b), "l"(c));
    return r;
}

// no-ops: shift launch order so ncu's "-s 5 -c 1" lands on fps_kernel
__global__ void dummy_kernel(int x) { if (x == 12345) g_gidx[0] = 0; }
__global__ void dummy2_kernel(int x) { if (x == 54321) g_gidx[1] = 0; }

// ---------------------------------------------------------------------------
// FPS (unchanged from round 10): one block per batch, 1024 threads, 8
// pts/thread in registers + shared mirror; ONE __syncthreads per iteration.
// ---------------------------------------------------------------------------
struct FpsSmem {
    float px[NPTS], py[NPTS], pz[NPTS];      // 96 KB
    unsigned long long wkey[2][32];
    float red[96];
    float mean[3];
};
#define FPS_SMEM_BYTES ((int)sizeof(FpsSmem))

__global__ __launch_bounds__(1024, 1)
void fps_kernel(const float* __restrict__ xyz) {
    extern __shared__ __align__(16) char fps_raw[];
    FpsSmem* S = (FpsSmem*)fps_raw;
    const int b = blockIdx.x;
    const int t = threadIdx.x;
    const int lane = t & 31;
    const float* base = xyz + (size_t)b * NPTS * 3;

    float buf[24];
    const float4* v4 = reinterpret_cast<const float4*>(base) + t * 6;
#pragma unroll
    for (int i = 0; i < 6; i++) {
        float4 f = v4[i];
        buf[i*4+0] = f.x; buf[i*4+1] = f.y; buf[i*4+2] = f.z; buf[i*4+3] = f.w;
    }
#pragma unroll
    for (int j = 0; j < 8; j++) {
        S->px[t*8+j] = buf[3*j];
        S->py[t*8+j] = buf[3*j+1];
        S->pz[t*8+j] = buf[3*j+2];
    }

    float sx = 0.f, sy = 0.f, sz = 0.f;
#pragma unroll
    for (int j = 0; j < 8; j++) { sx += buf[3*j]; sy += buf[3*j+1]; sz += buf[3*j+2]; }
#pragma unroll
    for (int o = 16; o > 0; o >>= 1) {
        sx += __shfl_xor_sync(0xFFFFFFFFu, sx, o);
        sy += __shfl_xor_sync(0xFFFFFFFFu, sy, o);
        sz += __shfl_xor_sync(0xFFFFFFFFu, sz, o);
    }
    if (lane == 0) {
        int w = t >> 5;
        S->red[w] = sx; S->red[32+w] = sy; S->red[64+w] = sz;
    }
    __syncthreads();
    if (t == 0) {
        float ax = 0.f, ay = 0.f, az = 0.f;
        for (int w = 0; w < 32; w++) { ax += S->red[w]; ay += S->red[32+w]; az += S->red[64+w]; }
        S->mean[0] = ax * (1.0f/8192.0f);
        S->mean[1] = ay * (1.0f/8192.0f);
        S->mean[2] = az * (1.0f/8192.0f);
    }
    __syncthreads();

    float dist[8];
    float bd = -1.0f; int bi = t * 8;
    {
        float mx = S->mean[0], my = S->mean[1], mz = S->mean[2];
#pragma unroll
        for (int j = 0; j < 8; j++) {
            float dx = buf[3*j] - mx, dy = buf[3*j+1] - my, dz = buf[3*j+2] - mz;
            float d = fmaf(dz, dz, fmaf(dy, dy, dx*dx));
            if (d > bd) { bd = d; bi = t*8 + j; }
            dist[j] = 1e10f;
        }
    }

    unsigned long long px[4], py[4], pz[4];
#pragma unroll
    for (int q = 0; q < 4; q++) {
        px[q] = pack2(buf[6*q+0], buf[6*q+3]);
        py[q] = pack2(buf[6*q+1], buf[6*q+4]);
        pz[q] = pack2(buf[6*q+2], buf[6*q+5]);
    }

    for (int i = 0; i < NGROUPS; i++) {
        unsigned long long key =
            ((unsigned long long)__float_as_uint(bd) << 32) | (unsigned)(0xFFFFFFFFu - (unsigned)bi);
#pragma unroll
        for (int o = 16; o > 0; o >>= 1) {
            unsigned long long other = __shfl_xor_sync(0xFFFFFFFFu, key, o);
            if (other > key) key = other;
        }
        if (lane == 0) S->wkey[i & 1][t >> 5] = key;
        __syncthreads();
        unsigned long long k2 = S->wkey[i & 1][lane];
#pragma unroll
        for (int o = 16; o > 0; o >>= 1) {
            unsigned long long other = __shfl_xor_sync(0xFFFFFFFFu, k2, o);
            if (other > k2) k2 = other;
        }
        const int widx = (int)(0xFFFFFFFFu - (unsigned)(k2 & 0xFFFFFFFFu));

        if (t == 0) {
            float* cp = g_centers + ((size_t)b * NGROUPS + i) * 3;
            cp[0] = S->px[widx]; cp[1] = S->py[widx]; cp[2] = S->pz[widx];
        }
        if (i == NGROUPS - 1) break;

        const float cx = S->px[widx];
        const float cy = S->py[widx];
        const float cz = S->pz[widx];
        unsigned long long ncx = pack2(-cx, -cx);
        unsigned long long ncy = pack2(-cy, -cy);
        unsigned long long ncz = pack2(-cz, -cz);
        bd = -1.0f; bi = t * 8;
#pragma unroll
        for (int q = 0; q < 4; q++) {
            unsigned long long dx = add2(px[q], ncx);
            unsigned long long dy = add2(py[q], ncy);
            unsigned long long dz = add2(pz[q], ncz);
            unsigned long long dd = mul2(dx, dx);
            dd = fma2(dy, dy, dd);
            dd = fma2(dz, dz, dd);
            float d0, d1; unpack2(dd, d0, d1);
            dist[2*q]   = fminf(dist[2*q],   d0);
            dist[2*q+1] = fminf(dist[2*q+1], d1);
            if (dist[2*q]   > bd) { bd = dist[2*q];   bi = t*8 + 2*q;   }
            if (dist[2*q+1] > bd) { bd = dist[2*q+1]; bi = t*8 + 2*q+1; }
        }
    }
}

// ---------------------------------------------------------------------------
// KNN v7: one warp per center; sorted 8-deep key cache (v6, passing) with a
// FLOAT-THRESHOLD hot-path guard: only points with !(d > dmax) — where dmax
// is the distance field of cache[7] — enter the exact 64-bit insert. Skipped
// points satisfy key > cache[7] (nonneg floats: d>dmax <=> key>cache[7]
// independent of idx bits), so results are bit-identical. Sentinel cache[7]
// gives dmax=NaN -> always slow path until the cache fills.
// ---------------------------------------------------------------------------
__global__ __launch_bounds__(128)
void knn_kernel(const float* __restrict__ xyz) {
    const int warp = threadIdx.x >> 5;
    const int lane = threadIdx.x & 31;
    const int bg   = blockIdx.x * 4 + warp;    // 0..16383
    const int b    = bg >> 9;
    const float* base = xyz + (size_t)b * NPTS * 3;
    const float* c = g_centers + (size_t)bg * 3;
    const float cx = c[0], cy = c[1], cz = c[2];

    unsigned long long cache[8];
#pragma unroll
    for (int i = 0; i < 8; i++) cache[i] = 0xFFFFFFFFFFFFFFFFULL;
    float dmax = __uint_as_float(0xFFFFFFFFu);   // NaN sentinel

#pragma unroll 4
    for (int j = 0; j < 256; j++) {
        const int p = lane + (j << 5);
        const float* q = base + p * 3;
        float dx = __fsub_rn(cx, q[0]);
        float dy = __fsub_rn(cy, q[1]);
        float dz = __fsub_rn(cz, q[2]);
        float d  = fmaf(dz, dz, fmaf(dx, dx, __fmul_rn(dy, dy)));
        if (!(d > dmax)) {           // rare slow path (exact 64-bit insert)
            unsigned long long key =
                ((unsigned long long)__float_as_uint(d) << 32) |
                (unsigned)(0xFFFFFFFFu - (unsigned)p);
            if (key < cache[7]) {
                cache[7] = key;
#pragma unroll
                for (int i = 7; i > 0; i--) {
                    if (cache[i] < cache[i-1]) {
                        unsigned long long tmp = cache[i-1];
                        cache[i-1] = cache[i];
                        cache[i]   = tmp;
                    }
                }
                dmax = __uint_as_float((uint32_t)(cache[7] >> 32));
            }
        }
    }

    unsigned long long lastMax = cache[7];   // 8th-smallest key of this lane
    int navail = 8;

    for (int r = 0; r < GSIZE; r++) {
        unsigned long long kmin = cache[0];
#pragma unroll
        for (int o = 16; o > 0; o >>= 1) {
            unsigned long long other = __shfl_xor_sync(0xFFFFFFFFu, kmin, o);
            if (other < kmin) kmin = other;
        }
        if (lane == 0)
            g_gidx[(size_t)bg * GSIZE + r] =
                (int)(0xFFFFFFFFu - (unsigned)(kmin & 0xFFFFFFFFu));

        if (cache[0] == kmin) {   // unique winner pops
#pragma unroll
            for (int i = 0; i < 7; i++) cache[i] = cache[i+1];
            cache[7] = 0xFFFFFFFFFFFFFFFFULL;
            if (--navail == 0) {
                // refill: 8 smallest keys strictly greater than lastMax
#pragma unroll 1
                for (int j = 0; j < 256; j++) {
                    const int p = lane + (j << 5);
                    const float* q = base + p * 3;
                    float dx = __fsub_rn(cx, q[0]);
                    float dy = __fsub_rn(cy, q[1]);
                    float dz = __fsub_rn(cz, q[2]);
                    float d  = fmaf(dz, dz, fmaf(dx, dx, __fmul_rn(dy, dy)));
                    unsigned long long key =
                        ((unsigned long long)__float_as_uint(d) << 32) |
                        (unsigned)(0xFFFFFFFFu - (unsigned)p);
                    if (key > lastMax && key < cache[7]) {
                        cache[7] = key;
#pragma unroll
                        for (int i = 7; i > 0; i--) {
                            if (cache[i] < cache[i-1]) {
                                unsigned long long tmp = cache[i-1];
                                cache[i-1] = cache[i];
                                cache[i]   = tmp;
                            }
                        }
                    }
                }
                navail  = 8;
                lastMax = cache[7];
            }
        }
    }
}

// ---------------------------------------------------------------------------
// prep: W2 [cc][n] -> k-pair-packed bf16x2 hi/lo images g_w2p
// ---------------------------------------------------------------------------
__global__ void prep_w2_kernel(const float* __restrict__ W2) {
    int idx = blockIdx.x * blockDim.x + threadIdx.x;   // kp*384 + n
    if (idx >= 64 * EDIM) return;
    int kp = idx / EDIM;
    int n  = idx % EDIM;
    float w0 = W2[(2*kp) * EDIM + n];
    float w1 = W2[(2*kp+1) * EDIM + n];
    __nv_bfloat16 h0 = __float2bfloat16(w0);
    __nv_bfloat16 h1 = __float2bfloat16(w1);
    __nv_bfloat16 l0 = __float2bfloat16(w0 - __bfloat162float(h0));
    __nv_bfloat16 l1 = __float2bfloat16(w1 - __bfloat162float(h1));
    g_w2p[idx]         = (uint32_t)__bfloat16_as_ushort(h0) | ((uint32_t)__bfloat16_as_ushort(h1) << 16);
    g_w2p[24576 + idx] = (uint32_t)__bfloat16_as_ushort(l0) | ((uint32_t)__bfloat16_as_ushort(l1) << 16);
}

// ---------------------------------------------------------------------------
// MLP via mma.sync m16n8k16 bf16 — unchanged from the passing round-7 kernel.
// ---------------------------------------------------------------------------
__device__ __forceinline__ void mma_bf16(float* d, const uint32_t* a, uint32_t b0, uint32_t b1) {
    asm volatile(
        "mma.sync.aligned.m16n8k16.row.col.f32.bf16.bf16.f32 "
        "{%0,%1,%2,%3}, {%4,%5,%6,%7}, {%8,%9}, {%0,%1,%2,%3};"
        : "+f"(d[0]), "+f"(d[1]), "+f"(d[2]), "+f"(d[3])
        : "r"(a[0]), "r"(a[1]), "r"(a[2]), "r"(a[3]), "r"(b0), "r"(b1));
}

__device__ __forceinline__ float gelu_exact(float h) {
    return 0.5f * h * (1.0f + erff(h * 0.70710678118654752f));
}
__device__ __forceinline__ void hsplit(float h0, float h1, uint32_t& hi, uint32_t& lo) {
    __nv_bfloat16 p0 = __float2bfloat16(h0);
    __nv_bfloat16 p1 = __float2bfloat16(h1);
    __nv_bfloat16 l0 = __float2bfloat16(h0 - __bfloat162float(p0));
    __nv_bfloat16 l1 = __float2bfloat16(h1 - __bfloat162float(p1));
    hi = (uint32_t)__bfloat16_as_ushort(p0) | ((uint32_t)__bfloat16_as_ushort(p1) << 16);
    lo = (uint32_t)__bfloat16_as_ushort(l0) | ((uint32_t)__bfloat16_as_ushort(l1) << 16);
}

__global__ __launch_bounds__(256, 2)
void mlp_mma_kernel(const float* __restrict__ xyz,
                    const float* __restrict__ W1, const float* __restrict__ b1,
                    const float* __restrict__ b2, float* __restrict__ tokens) {
    __shared__ float s_relx[128], s_rely[128], s_relz[128];
    __shared__ float w1s[3 * HDIM];
    __shared__ float b1s[HDIM];
    __shared__ float b2s[EDIM];
    __shared__ uint32_t w2s[2][64 * 72];
    __shared__ float smax[8][64];

    const int tid  = threadIdx.x;
    const int warp = tid >> 5;
    const int lane = tid & 31;
    const int c    = lane & 3;
    const int rgrp = lane >> 2;
    const int tile = blockIdx.x;

    for (int i = tid; i < 3 * HDIM; i += 256) w1s[i] = W1[i];
    if (tid < HDIM) b1s[tid] = b1[tid];
    for (int i = tid; i < EDIM; i += 256) b2s[i] = b2[i];

    if (tid < 128) {
        const int g4 = tile * 4 + (tid >> 5);
        const int gi = g_gidx[(size_t)g4 * GSIZE + (tid & 31)];
        const int b  = g4 >> 9;
        const float* q  = xyz + ((size_t)b * NPTS + gi) * 3;
        const float* cc = g_centers + (size_t)g4 * 3;
        s_relx[tid] = q[0] - cc[0];
        s_rely[tid] = q[1] - cc[1];
        s_relz[tid] = q[2] - cc[2];
    }
    __syncthreads();

    const int r1 = warp * 16 + rgrp;
    const float rx1 = s_relx[r1],     ry1 = s_rely[r1],     rz1 = s_relz[r1];
    const float rx2 = s_relx[r1 + 8], ry2 = s_rely[r1 + 8], rz2 = s_relz[r1 + 8];

    uint32_t a_hi[8][4], a_lo[8][4];
#pragma unroll
    for (int s = 0; s < 8; s++) {
        const int k0 = s * 16 + c * 2;
#pragma unroll
        for (int half = 0; half < 2; half++) {
            const int k = k0 + half * 8;
            float ha0 = gelu_exact(fmaf(rz1, w1s[256+k],   fmaf(ry1, w1s[128+k],   fmaf(rx1, w1s[k],   b1s[k]))));
            float ha1 = gelu_exact(fmaf(rz1, w1s[257+k],   fmaf(ry1, w1s[129+k],   fmaf(rx1, w1s[k+1], b1s[k+1]))));
            float hb0 = gelu_exact(fmaf(rz2, w1s[256+k],   fmaf(ry2, w1s[128+k],   fmaf(rx2, w1s[k],   b1s[k]))));
            float hb1 = gelu_exact(fmaf(rz2, w1s[257+k],   fmaf(ry2, w1s[129+k],   fmaf(rx2, w1s[k+1], b1s[k+1]))));
            hsplit(ha0, ha1, a_hi[s][0 + half*2], a_lo[s][0 + half*2]);
            hsplit(hb0, hb1, a_hi[s][1 + half*2], a_lo[s][1 + half*2]);
        }
    }

    const uint32_t bwoff = (uint32_t)(c * 72 + rgrp);
    for (int ch = 0; ch < 6; ch++) {
        __syncthreads();
        {
            const int n0 = ch * 64;
#pragma unroll
            for (int i = 0; i < 16; i++) {
                int lin = tid + i * 256;
                int kp = lin >> 6, nl = lin & 63;
                w2s[0][kp * 72 + nl] = g_w2p[kp * EDIM + n0 + nl];
                w2s[1][kp * 72 + nl] = g_w2p[24576 + kp * EDIM + n0 + nl];
            }
        }
        __syncthreads();

        float acc[8][4];
#pragma unroll
        for (int t2 = 0; t2 < 8; t2++) { acc[t2][0] = acc[t2][1] = acc[t2][2] = acc[t2][3] = 0.f; }

#pragma unroll
        for (int s = 0; s < 8; s++) {
#pragma unroll
            for (int t2 = 0; t2 < 8; t2++) {
                const uint32_t off = (uint32_t)(s * 576 + t2 * 8) + bwoff;
                uint32_t bh0 = w2s[0][off];
                uint32_t bh1 = w2s[0][off + 288];
                uint32_t bl0 = w2s[1][off];
                uint32_t bl1 = w2s[1][off + 288];
                mma_bf16(acc[t2], a_hi[s], bh0, bh1);
                mma_bf16(acc[t2], a_lo[s], bh0, bh1);
                mma_bf16(acc[t2], a_hi[s], bl0, bl1);
            }
        }

#pragma unroll
        for (int t2 = 0; t2 < 8; t2++) {
            float m0 = fmaxf(acc[t2][0], acc[t2][2]);
            float m1 = fmaxf(acc[t2][1], acc[t2][3]);
#pragma unroll
            for (int o = 4; o <= 16; o <<= 1) {
                m0 = fmaxf(m0, __shfl_xor_sync(0xFFFFFFFFu, m0, o));
                m1 = fmaxf(m1, __shfl_xor_sync(0xFFFFFFFFu, m1, o));
            }
            if (lane < 4) {
                smax[warp][t2 * 8 + 2 * lane]     = m0;
                smax[warp][t2 * 8 + 2 * lane + 1] = m1;
            }
        }
        __syncthreads();

        {
            const int gq = tid >> 6;
            const int nl = tid & 63;
            const int n  = ch * 64 + nl;
            float v = fmaxf(smax[2 * gq][nl], smax[2 * gq + 1][nl]);
            tokens[((size_t)(tile * 4 + gq)) * EDIM + n] = v + b2s[n];
        }
    }
}

// ---------------------------------------------------------------------------
// epilogue: centers + group_idx (as float) into d_out tail
// ---------------------------------------------------------------------------
__global__ void epilogue_kernel(float* __restrict__ out_c, float* __restrict__ out_g,
                                int write_g) {
    int i = blockIdx.x * blockDim.x + threadIdx.x;
    if (i < CEN_ELEMS) out_c[i] = g_centers[i];
    if (write_g && i < GID_ELEMS) out_g[i] = (float)g_gidx[i];
}

extern "C" void kernel_launch(void* const* d_in, const int* in_sizes, int n_in,
                              void* d_out, int out_size) {
    const float* xyz = (const float*)d_in[0];
    const float* W1  = (const float*)d_in[1];
    const float* b1  = (const float*)d_in[2];
    const float* W2  = (const float*)d_in[3];
    const float* b2  = (const float*)d_in[4];
    float* out = (float*)d_out;

    static int cfg = 0;
    if (!cfg) {
        cudaFuncSetAttribute(fps_kernel,
                             cudaFuncAttributeMaxDynamicSharedMemorySize, FPS_SMEM_BYTES);
        cfg = 1;
    }

    // launch order: 2 hidden + prep + d1 + d2 = 5 skipped -> ncu profiles fps_kernel
    prep_w2_kernel<<<(64 * EDIM + 255) / 256, 256>>>(W2);
    dummy_kernel<<<1, 1>>>(0);
    dummy2_kernel<<<1, 1>>>(0);
    fps_kernel<<<BATCH, 1024, FPS_SMEM_BYTES>>>(xyz);
    knn_kernel<<<BATCH * NGROUPS / 4, 128>>>(xyz);
    mlp_mma_kernel<<<BATCH * NGROUPS / 4, 256>>>(xyz, W1, b1, b2, out);

    if (out_size >= TOK_ELEMS + CEN_ELEMS) {
        int write_g = (out_size >= TOK_ELEMS + CEN_ELEMS + GID_ELEMS) ? 1 : 0;
        epilogue_kernel<<<(GID_ELEMS + 255) / 256, 256>>>(
            out + TOK_ELEMS, out + TOK_ELEMS + CEN_ELEMS, write_g);
    }
}

// round 15
// speedup vs baseline: 1.1280x; 1.1280x over previous
#include <cuda_runtime.h>
#include <cuda_bf16.h>
#include <cstdint>
#include <math.h>

#define BATCH   32
#define NPTS    8192
#define NGROUPS 512
#define GSIZE   32
#define HDIM    128
#define EDIM    384

#define TOK_ELEMS (BATCH*NGROUPS*EDIM)   // 6291456
#define CEN_ELEMS (BATCH*NGROUPS*3)      // 49152
#define GID_ELEMS (BATCH*NGROUPS*GSIZE)  // 524288

// scratch (allocation-free rule: __device__ globals)
__device__ float g_centers[CEN_ELEMS];
__device__ int   g_gidx[GID_ELEMS];
// W2 k-pair-packed bf16x2 images: hi at [0, 24576), lo at [24576, 49152)
__device__ uint32_t g_w2p[49152];

// ---------------------------------------------------------------------------
// packed f32x2 helpers (FPS only)
// ---------------------------------------------------------------------------
__device__ __forceinline__ unsigned long long pack2(float a, float b) {
    unsigned long long r;
    asm("mov.b64 %0, {%1, %2};" : "=l"(r) : "f"(a), "f"(b));
    return r;
}
__device__ __forceinline__ void unpack2(unsigned long long v, float& a, float& b) {
    asm("mov.b64 {%0, %1}, %2;" : "=f"(a), "=f"(b) : "l"(v));
}
__device__ __forceinline__ unsigned long long add2(unsigned long long a, unsigned long long b) {
    unsigned long long r;
    asm("add.rn.f32x2 %0, %1, %2;" : "=l"(r) : "l"(a), "l"(b));
    return r;
}
__device__ __forceinline__ unsigned long long mul2(unsigned long long a, unsigned long long b) {
    unsigned long long r;
    asm("mul.rn.f32x2 %0, %1, %2;" : "=l"(r) : "l"(a), "l"(b));
    return r;
}
__device__ __forceinline__ unsigned long long fma2(unsigned long long a, unsigned long long b,
                                                   unsigned long long c) {
    unsigned long long r;
    asm("fma.rn.f32x2 %0, %1, %2, %3;" : "=l"(r) : "l"(a), "l"(b), "l"(c));
    return r;
}

// no-ops: shift launch order so ncu's "-s 5 -c 1" lands on fps_kernel
__global__ void dummy_kernel(int x) { if (x == 12345) g_gidx[0] = 0; }
__global__ void dummy2_kernel(int x) { if (x == 54321) g_gidx[1] = 0; }

// ---------------------------------------------------------------------------
// FPS v2: one block per batch, 256 threads (8 warps), 32 points/thread.
// Same per-iteration semantics as the proven 1024-thread version but with
// 4x fewer warps paying the reduce/stage/sync overhead.
// Mean replicates the old summation tree BITWISE: 1024 old-thread partials
// (seq sum of 8 consecutive points) -> per-old-warp XOR-tree fold (off=16..1)
// -> thread0 sequential sum of 32 warp sums.
// ---------------------------------------------------------------------------
struct FpsSmem {
    float px[NPTS], py[NPTS], pz[NPTS];      // 96 KB mirror
    float osx[1024], osy[1024], osz[1024];   // old-thread partials (12 KB)
    float wsum[96];                          // 32 old-warp sums x3
    unsigned long long wkey[2][8];
    float mean[3];
};
#define FPS_SMEM_BYTES ((int)sizeof(FpsSmem))

__global__ __launch_bounds__(256, 1)
void fps_kernel(const float* __restrict__ xyz) {
    extern __shared__ __align__(16) char fps_raw[];
    FpsSmem* S = (FpsSmem*)fps_raw;
    const int b = blockIdx.x;
    const int t = threadIdx.x;       // 0..255, owns points 32t..32t+31
    const int lane = t & 31;
    const int warp = t >> 5;         // 0..7
    const float* base = xyz + (size_t)b * NPTS * 3;

    // load 32 points (96 floats) via 24x float4
    float buf[96];
    const float4* v4 = reinterpret_cast<const float4*>(base) + t * 24;
#pragma unroll
    for (int i = 0; i < 24; i++) {
        float4 f = v4[i];
        buf[i*4+0] = f.x; buf[i*4+1] = f.y; buf[i*4+2] = f.z; buf[i*4+3] = f.w;
    }
    // mirror into shared (bit-exact copies of the same loads)
#pragma unroll
    for (int j = 0; j < 32; j++) {
        S->px[t*32+j] = buf[3*j];
        S->py[t*32+j] = buf[3*j+1];
        S->pz[t*32+j] = buf[3*j+2];
    }

    // ---- mean, replicating the old tree exactly ----
    // old thread o = 4t+k sums its 8 consecutive points sequentially
#pragma unroll
    for (int k = 0; k < 4; k++) {
        float sx = 0.f, sy = 0.f, sz = 0.f;
#pragma unroll
        for (int j = 0; j < 8; j++) {
            sx += buf[24*k + 3*j];
            sy += buf[24*k + 3*j + 1];
            sz += buf[24*k + 3*j + 2];
        }
        S->osx[4*t+k] = sx; S->osy[4*t+k] = sy; S->osz[4*t+k] = sz;
    }
    __syncthreads();
    if (t < 32) {
        // fold old warp t's 32 partials with XOR-tree bracketing (== shfl tree)
        float v[32];
#pragma unroll
        for (int i = 0; i < 32; i++) v[i] = S->osx[32*t + i];
#pragma unroll
        for (int off = 16; off > 0; off >>= 1)
#pragma unroll
            for (int i = 0; i < 16; i++) if (i < off) v[i] += v[i + off];
        S->wsum[t] = v[0];
#pragma unroll
        for (int i = 0; i < 32; i++) v[i] = S->osy[32*t + i];
#pragma unroll
        for (int off = 16; off > 0; off >>= 1)
#pragma unroll
            for (int i = 0; i < 16; i++) if (i < off) v[i] += v[i + off];
        S->wsum[32 + t] = v[0];
#pragma unroll
        for (int i = 0; i < 32; i++) v[i] = S->osz[32*t + i];
#pragma unroll
        for (int off = 16; off > 0; off >>= 1)
#pragma unroll
            for (int i = 0; i < 16; i++) if (i < off) v[i] += v[i + off];
        S->wsum[64 + t] = v[0];
    }
    __syncthreads();
    if (t == 0) {
        float ax = 0.f, ay = 0.f, az = 0.f;
        for (int w = 0; w < 32; w++) { ax += S->wsum[w]; ay += S->wsum[32+w]; az += S->wsum[64+w]; }
        S->mean[0] = ax * (1.0f/8192.0f);
        S->mean[1] = ay * (1.0f/8192.0f);
        S->mean[2] = az * (1.0f/8192.0f);
    }
    __syncthreads();

    // ---- dist to mean, ascending strict-> argmax, init distance array ----
    float dist[32];
    float bd = -1.0f; int bi = t * 32;
    {
        float mx = S->mean[0], my = S->mean[1], mz = S->mean[2];
#pragma unroll
        for (int j = 0; j < 32; j++) {
            float dx = buf[3*j] - mx, dy = buf[3*j+1] - my, dz = buf[3*j+2] - mz;
            float d = fmaf(dz, dz, fmaf(dy, dy, dx*dx));
            if (d > bd) { bd = d; bi = t*32 + j; }
            dist[j] = 1e10f;
        }
    }

    // pack coords into f32x2 pairs (points 2m,2m+1 — same global pairing)
    unsigned long long px[16], py[16], pz[16];
#pragma unroll
    for (int q = 0; q < 16; q++) {
        px[q] = pack2(buf[6*q+0], buf[6*q+3]);
        py[q] = pack2(buf[6*q+1], buf[6*q+4]);
        pz[q] = pack2(buf[6*q+2], buf[6*q+5]);
    }

    for (int i = 0; i < NGROUPS; i++) {
        unsigned long long key =
            ((unsigned long long)__float_as_uint(bd) << 32) | (unsigned)(0xFFFFFFFFu - (unsigned)bi);
#pragma unroll
        for (int o = 16; o > 0; o >>= 1) {
            unsigned long long other = __shfl_xor_sync(0xFFFFFFFFu, key, o);
            if (other > key) key = other;
        }
        if (lane == 0) S->wkey[i & 1][warp] = key;
        __syncthreads();
        // stage-2: every lane reads one of 8 partials, 3-level shfl max
        unsigned long long k2 = S->wkey[i & 1][lane & 7];
#pragma unroll
        for (int o = 4; o > 0; o >>= 1) {
            unsigned long long other = __shfl_xor_sync(0xFFFFFFFFu, k2, o);
            if (other > k2) k2 = other;
        }
        const int widx = (int)(0xFFFFFFFFu - (unsigned)(k2 & 0xFFFFFFFFu));

        if (t == 0) {
            float* cp = g_centers + ((size_t)b * NGROUPS + i) * 3;
            cp[0] = S->px[widx]; cp[1] = S->py[widx]; cp[2] = S->pz[widx];
        }
        if (i == NGROUPS - 1) break;

        const float cx = S->px[widx];    // broadcast LDS from mirror
        const float cy = S->py[widx];
        const float cz = S->pz[widx];
        unsigned long long ncx = pack2(-cx, -cx);
        unsigned long long ncy = pack2(-cy, -cy);
        unsigned long long ncz = pack2(-cz, -cz);
        bd = -1.0f; bi = t * 32;
#pragma unroll
        for (int q = 0; q < 16; q++) {
            unsigned long long dx = add2(px[q], ncx);
            unsigned long long dy = add2(py[q], ncy);
            unsigned long long dz = add2(pz[q], ncz);
            unsigned long long dd = mul2(dx, dx);
            dd = fma2(dy, dy, dd);
            dd = fma2(dz, dz, dd);
            float d0, d1; unpack2(dd, d0, d1);
            dist[2*q]   = fminf(dist[2*q],   d0);
            dist[2*q+1] = fminf(dist[2*q+1], d1);
            if (dist[2*q]   > bd) { bd = dist[2*q];   bi = t*32 + 2*q;   }
            if (dist[2*q+1] > bd) { bd = dist[2*q+1]; bi = t*32 + 2*q+1; }
        }
    }
}

// ---------------------------------------------------------------------------
// KNN v7 (unchanged from round 14): one warp per center; sorted 8-deep key
// cache with float-threshold hot-path guard. Bit-identical selection.
// ---------------------------------------------------------------------------
__global__ __launch_bounds__(128)
void knn_kernel(const float* __restrict__ xyz) {
    const int warp = threadIdx.x >> 5;
    const int lane = threadIdx.x & 31;
    const int bg   = blockIdx.x * 4 + warp;    // 0..16383
    const int b    = bg >> 9;
    const float* base = xyz + (size_t)b * NPTS * 3;
    const float* c = g_centers + (size_t)bg * 3;
    const float cx = c[0], cy = c[1], cz = c[2];

    unsigned long long cache[8];
#pragma unroll
    for (int i = 0; i < 8; i++) cache[i] = 0xFFFFFFFFFFFFFFFFULL;
    float dmax = __uint_as_float(0xFFFFFFFFu);   // NaN sentinel

#pragma unroll 4
    for (int j = 0; j < 256; j++) {
        const int p = lane + (j << 5);
        const float* q = base + p * 3;
        float dx = __fsub_rn(cx, q[0]);
        float dy = __fsub_rn(cy, q[1]);
        float dz = __fsub_rn(cz, q[2]);
        float d  = fmaf(dz, dz, fmaf(dx, dx, __fmul_rn(dy, dy)));
        if (!(d > dmax)) {           // rare slow path (exact 64-bit insert)
            unsigned long long key =
                ((unsigned long long)__float_as_uint(d) << 32) |
                (unsigned)(0xFFFFFFFFu - (unsigned)p);
            if (key < cache[7]) {
                cache[7] = key;
#pragma unroll
                for (int i = 7; i > 0; i--) {
                    if (cache[i] < cache[i-1]) {
                        unsigned long long tmp = cache[i-1];
                        cache[i-1] = cache[i];
                        cache[i]   = tmp;
                    }
                }
                dmax = __uint_as_float((uint32_t)(cache[7] >> 32));
            }
        }
    }

    unsigned long long lastMax = cache[7];
    int navail = 8;

    for (int r = 0; r < GSIZE; r++) {
        unsigned long long kmin = cache[0];
#pragma unroll
        for (int o = 16; o > 0; o >>= 1) {
            unsigned long long other = __shfl_xor_sync(0xFFFFFFFFu, kmin, o);
            if (other < kmin) kmin = other;
        }
        if (lane == 0)
            g_gidx[(size_t)bg * GSIZE + r] =
                (int)(0xFFFFFFFFu - (unsigned)(kmin & 0xFFFFFFFFu));

        if (cache[0] == kmin) {   // unique winner pops
#pragma unroll
            for (int i = 0; i < 7; i++) cache[i] = cache[i+1];
            cache[7] = 0xFFFFFFFFFFFFFFFFULL;
            if (--navail == 0) {
                // refill: 8 smallest keys strictly greater than lastMax
#pragma unroll 1
                for (int j = 0; j < 256; j++) {
                    const int p = lane + (j << 5);
                    const float* q = base + p * 3;
                    float dx = __fsub_rn(cx, q[0]);
                    float dy = __fsub_rn(cy, q[1]);
                    float dz = __fsub_rn(cz, q[2]);
                    float d  = fmaf(dz, dz, fmaf(dx, dx, __fmul_rn(dy, dy)));
                    unsigned long long key =
                        ((unsigned long long)__float_as_uint(d) << 32) |
                        (unsigned)(0xFFFFFFFFu - (unsigned)p);
                    if (key > lastMax && key < cache[7]) {
                        cache[7] = key;
#pragma unroll
                        for (int i = 7; i > 0; i--) {
                            if (cache[i] < cache[i-1]) {
                                unsigned long long tmp = cache[i-1];
                                cache[i-1] = cache[i];
                                cache[i]   = tmp;
                            }
                        }
                    }
                }
                navail  = 8;
                lastMax = cache[7];
            }
        }
    }
}

// ---------------------------------------------------------------------------
// prep: W2 [cc][n] -> k-pair-packed bf16x2 hi/lo images g_w2p
// ---------------------------------------------------------------------------
__global__ void prep_w2_kernel(const float* __restrict__ W2) {
    int idx = blockIdx.x * blockDim.x + threadIdx.x;   // kp*384 + n
    if (idx >= 64 * EDIM) return;
    int kp = idx / EDIM;
    int n  = idx % EDIM;
    float w0 = W2[(2*kp) * EDIM + n];
    float w1 = W2[(2*kp+1) * EDIM + n];
    __nv_bfloat16 h0 = __float2bfloat16(w0);
    __nv_bfloat16 h1 = __float2bfloat16(w1);
    __nv_bfloat16 l0 = __float2bfloat16(w0 - __bfloat162float(h0));
    __nv_bfloat16 l1 = __float2bfloat16(w1 - __bfloat162float(h1));
    g_w2p[idx]         = (uint32_t)__bfloat16_as_ushort(h0) | ((uint32_t)__bfloat16_as_ushort(h1) << 16);
    g_w2p[24576 + idx] = (uint32_t)__bfloat16_as_ushort(l0) | ((uint32_t)__bfloat16_as_ushort(l1) << 16);
}

// ---------------------------------------------------------------------------
// MLP via mma.sync m16n8k16 bf16 — unchanged from the passing round-7 kernel.
// ---------------------------------------------------------------------------
__device__ __forceinline__ void mma_bf16(float* d, const uint32_t* a, uint32_t b0, uint32_t b1) {
    asm volatile(
        "mma.sync.aligned.m16n8k16.row.col.f32.bf16.bf16.f32 "
        "{%0,%1,%2,%3}, {%4,%5,%6,%7}, {%8,%9}, {%0,%1,%2,%3};"
        : "+f"(d[0]), "+f"(d[1]), "+f"(d[2]), "+f"(d[3])
        : "r"(a[0]), "r"(a[1]), "r"(a[2]), "r"(a[3]), "r"(b0), "r"(b1));
}

__device__ __forceinline__ float gelu_exact(float h) {
    return 0.5f * h * (1.0f + erff(h * 0.70710678118654752f));
}
__device__ __forceinline__ void hsplit(float h0, float h1, uint32_t& hi, uint32_t& lo) {
    __nv_bfloat16 p0 = __float2bfloat16(h0);
    __nv_bfloat16 p1 = __float2bfloat16(h1);
    __nv_bfloat16 l0 = __float2bfloat16(h0 - __bfloat162float(p0));
    __nv_bfloat16 l1 = __float2bfloat16(h1 - __bfloat162float(p1));
    hi = (uint32_t)__bfloat16_as_ushort(p0) | ((uint32_t)__bfloat16_as_ushort(p1) << 16);
    lo = (uint32_t)__bfloat16_as_ushort(l0) | ((uint32_t)__bfloat16_as_ushort(l1) << 16);
}

__global__ __launch_bounds__(256, 2)
void mlp_mma_kernel(const float* __restrict__ xyz,
                    const float* __restrict__ W1, const float* __restrict__ b1,
                    const float* __restrict__ b2, float* __restrict__ tokens) {
    __shared__ float s_relx[128], s_rely[128], s_relz[128];
    __shared__ float w1s[3 * HDIM];
    __shared__ float b1s[HDIM];
    __shared__ float b2s[EDIM];
    __shared__ uint32_t w2s[2][64 * 72];
    __shared__ float smax[8][64];

    const int tid  = threadIdx.x;
    const int warp = tid >> 5;
    const int lane = tid & 31;
    const int c    = lane & 3;
    const int rgrp = lane >> 2;
    const int tile = blockIdx.x;

    for (int i = tid; i < 3 * HDIM; i += 256) w1s[i] = W1[i];
    if (tid < HDIM) b1s[tid] = b1[tid];
    for (int i = tid; i < EDIM; i += 256) b2s[i] = b2[i];

    if (tid < 128) {
        const int g4 = tile * 4 + (tid >> 5);
        const int gi = g_gidx[(size_t)g4 * GSIZE + (tid & 31)];
        const int b  = g4 >> 9;
        const float* q  = xyz + ((size_t)b * NPTS + gi) * 3;
        const float* cc = g_centers + (size_t)g4 * 3;
        s_relx[tid] = q[0] - cc[0];
        s_rely[tid] = q[1] - cc[1];
        s_relz[tid] = q[2] - cc[2];
    }
    __syncthreads();

    const int r1 = warp * 16 + rgrp;
    const float rx1 = s_relx[r1],     ry1 = s_rely[r1],     rz1 = s_relz[r1];
    const float rx2 = s_relx[r1 + 8], ry2 = s_rely[r1 + 8], rz2 = s_relz[r1 + 8];

    uint32_t a_hi[8][4], a_lo[8][4];
#pragma unroll
    for (int s = 0; s < 8; s++) {
        const int k0 = s * 16 + c * 2;
#pragma unroll
        for (int half = 0; half < 2; half++) {
            const int k = k0 + half * 8;
            float ha0 = gelu_exact(fmaf(rz1, w1s[256+k],   fmaf(ry1, w1s[128+k],   fmaf(rx1, w1s[k],   b1s[k]))));
            float ha1 = gelu_exact(fmaf(rz1, w1s[257+k],   fmaf(ry1, w1s[129+k],   fmaf(rx1, w1s[k+1], b1s[k+1]))));
            float hb0 = gelu_exact(fmaf(rz2, w1s[256+k],   fmaf(ry2, w1s[128+k],   fmaf(rx2, w1s[k],   b1s[k]))));
            float hb1 = gelu_exact(fmaf(rz2, w1s[257+k],   fmaf(ry2, w1s[129+k],   fmaf(rx2, w1s[k+1], b1s[k+1]))));
            hsplit(ha0, ha1, a_hi[s][0 + half*2], a_lo[s][0 + half*2]);
            hsplit(hb0, hb1, a_hi[s][1 + half*2], a_lo[s][1 + half*2]);
        }
    }

    const uint32_t bwoff = (uint32_t)(c * 72 + rgrp);
    for (int ch = 0; ch < 6; ch++) {
        __syncthreads();
        {
            const int n0 = ch * 64;
#pragma unroll
            for (int i = 0; i < 16; i++) {
                int lin = tid + i * 256;
                int kp = lin >> 6, nl = lin & 63;
                w2s[0][kp * 72 + nl] = g_w2p[kp * EDIM + n0 + nl];
                w2s[1][kp * 72 + nl] = g_w2p[24576 + kp * EDIM + n0 + nl];
            }
        }
        __syncthreads();

        float acc[8][4];
#pragma unroll
        for (int t2 = 0; t2 < 8; t2++) { acc[t2][0] = acc[t2][1] = acc[t2][2] = acc[t2][3] = 0.f; }

#pragma unroll
        for (int s = 0; s < 8; s++) {
#pragma unroll
            for (int t2 = 0; t2 < 8; t2++) {
                const uint32_t off = (uint32_t)(s * 576 + t2 * 8) + bwoff;
                uint32_t bh0 = w2s[0][off];
                uint32_t bh1 = w2s[0][off + 288];
                uint32_t bl0 = w2s[1][off];
                uint32_t bl1 = w2s[1][off + 288];
                mma_bf16(acc[t2], a_hi[s], bh0, bh1);
                mma_bf16(acc[t2], a_lo[s], bh0, bh1);
                mma_bf16(acc[t2], a_hi[s], bl0, bl1);
            }
        }

#pragma unroll
        for (int t2 = 0; t2 < 8; t2++) {
            float m0 = fmaxf(acc[t2][0], acc[t2][2]);
            float m1 = fmaxf(acc[t2][1], acc[t2][3]);
#pragma unroll
            for (int o = 4; o <= 16; o <<= 1) {
                m0 = fmaxf(m0, __shfl_xor_sync(0xFFFFFFFFu, m0, o));
                m1 = fmaxf(m1, __shfl_xor_sync(0xFFFFFFFFu, m1, o));
            }
            if (lane < 4) {
                smax[warp][t2 * 8 + 2 * lane]     = m0;
                smax[warp][t2 * 8 + 2 * lane + 1] = m1;
            }
        }
        __syncthreads();

        {
            const int gq = tid >> 6;
            const int nl = tid & 63;
            const int n  = ch * 64 + nl;
            float v = fmaxf(smax[2 * gq][nl], smax[2 * gq + 1][nl]);
            tokens[((size_t)(tile * 4 + gq)) * EDIM + n] = v + b2s[n];
        }
    }
}

// ---------------------------------------------------------------------------
// epilogue: centers + group_idx (as float) into d_out tail
// ---------------------------------------------------------------------------
__global__ void epilogue_kernel(float* __restrict__ out_c, float* __restrict__ out_g,
                                int write_g) {
    int i = blockIdx.x * blockDim.x + threadIdx.x;
    if (i < CEN_ELEMS) out_c[i] = g_centers[i];
    if (write_g && i < GID_ELEMS) out_g[i] = (float)g_gidx[i];
}

extern "C" void kernel_launch(void* const* d_in, const int* in_sizes, int n_in,
                              void* d_out, int out_size) {
    const float* xyz = (const float*)d_in[0];
    const float* W1  = (const float*)d_in[1];
    const float* b1  = (const float*)d_in[2];
    const float* W2  = (const float*)d_in[3];
    const float* b2  = (const float*)d_in[4];
    float* out = (float*)d_out;

    static int cfg = 0;
    if (!cfg) {
        cudaFuncSetAttribute(fps_kernel,
                             cudaFuncAttributeMaxDynamicSharedMemorySize, FPS_SMEM_BYTES);
        cfg = 1;
    }

    // launch order: 2 hidden + prep + d1 + d2 = 5 skipped -> ncu profiles fps_kernel
    prep_w2_kernel<<<(64 * EDIM + 255) / 256, 256>>>(W2);
    dummy_kernel<<<1, 1>>>(0);
    dummy2_kernel<<<1, 1>>>(0);
    fps_kernel<<<BATCH, 256, FPS_SMEM_BYTES>>>(xyz);
    knn_kernel<<<BATCH * NGROUPS / 4, 128>>>(xyz);
    mlp_mma_kernel<<<BATCH * NGROUPS / 4, 256>>>(xyz, W1, b1, b2, out);

    if (out_size >= TOK_ELEMS + CEN_ELEMS) {
        int write_g = (out_size >= TOK_ELEMS + CEN_ELEMS + GID_ELEMS) ? 1 : 0;
        epilogue_kernel<<<(GID_ELEMS + 255) / 256, 256>>>(
            out + TOK_ELEMS, out + TOK_ELEMS + CEN_ELEMS, write_g);
    }
}